// round 11
// baseline (speedup 1.0000x reference)
#include <cuda_runtime.h>
#include <cuda_bf16.h>
#include <math.h>

// ---------------- problem constants ----------------
#define Bn     32
#define Sn     2304
#define Dn     1280
#define Hn     16
#define HDn    96
#define HHD    1536      // Hn*HDn
#define Ln     64
#define INTERn 5120
#define DEPTHn 6
#define EPSf   1e-5f

// ---------------- scratch: __device__ globals (no cudaMalloc allowed) ----------------
__device__ float g_xhat[(size_t)Bn*Sn*Dn];      // normalized context (layer-independent)
__device__ float g_lat [(size_t)Bn*Ln*Dn];      // latent residual stream
__device__ float g_lhat[(size_t)Bn*Ln*Dn];      // LN(lat) for attention block
__device__ float g_mlph[(size_t)Bn*Ln*Dn];      // LN(lat) for MLP block
__device__ float g_Kc  [(size_t)Bn*Sn*HHD];     // context K (head-LN applied in place)
__device__ float g_Vc  [(size_t)Bn*Sn*HHD];     // context V
__device__ float g_Q   [(size_t)Bn*Ln*HHD];
__device__ float g_Kl  [(size_t)Bn*Ln*HHD];     // latent K
__device__ float g_Vl  [(size_t)Bn*Ln*HHD];     // latent V
__device__ float g_att [(size_t)Bn*Ln*HHD];     // attention output (heads merged)
__device__ float g_hid [(size_t)Bn*Ln*INTERn];  // MLP hidden

// ---------------- helpers ----------------
__device__ __forceinline__ unsigned f2tf(float x) {
    unsigned r;
    asm("cvt.rna.tf32.f32 %0, %1;" : "=r"(r) : "f"(x));
    return r;
}

__device__ __forceinline__ void mma_tf32(float* c, const unsigned* a, const unsigned* b) {
    asm volatile(
        "mma.sync.aligned.m16n8k8.row.col.f32.tf32.tf32.f32 "
        "{%0,%1,%2,%3}, {%4,%5,%6,%7}, {%8,%9}, {%0,%1,%2,%3};\n"
        : "+f"(c[0]), "+f"(c[1]), "+f"(c[2]), "+f"(c[3])
        : "r"(a[0]), "r"(a[1]), "r"(a[2]), "r"(a[3]), "r"(b[0]), "r"(b[1]));
}

// ---------------- row LayerNorm, width = 1280 ----------------
template<bool AFF>
__global__ __launch_bounds__(256) void ln_kernel(
    const float* __restrict__ in, float* __restrict__ out,
    const float* __restrict__ g, const float* __restrict__ b)
{
    __shared__ float row[Dn];
    __shared__ float red[8];
    __shared__ float stat[2];
    const int r = blockIdx.x, tid = threadIdx.x;
    const int lane = tid & 31, w = tid >> 5;
    const float* x = in + (size_t)r * Dn;

    float s = 0.f;
    for (int i = tid; i < Dn; i += 256) { float v = x[i]; row[i] = v; s += v; }
    #pragma unroll
    for (int o = 16; o; o >>= 1) s += __shfl_xor_sync(0xffffffffu, s, o);
    if (lane == 0) red[w] = s;
    __syncthreads();
    if (tid == 0) { float t = 0.f; for (int j = 0; j < 8; j++) t += red[j]; stat[0] = t * (1.f/Dn); }
    __syncthreads();
    const float mean = stat[0];

    float s2 = 0.f;
    for (int i = tid; i < Dn; i += 256) { float d = row[i] - mean; s2 += d * d; }
    #pragma unroll
    for (int o = 16; o; o >>= 1) s2 += __shfl_xor_sync(0xffffffffu, s2, o);
    if (lane == 0) red[w] = s2;
    __syncthreads();
    if (tid == 0) { float t = 0.f; for (int j = 0; j < 8; j++) t += red[j]; stat[1] = rsqrtf(t * (1.f/Dn) + EPSf); }
    __syncthreads();
    const float rstd = stat[1];

    float* o = out + (size_t)r * Dn;
    for (int i = tid; i < Dn; i += 256) {
        float v = (row[i] - mean) * rstd;
        o[i] = AFF ? (v * g[i] + b[i]) : v;
    }
}

// ---------------- broadcast latents to batch ----------------
__global__ void bcast_lat(const float* __restrict__ lat0, float* __restrict__ out) {
    int i = blockIdx.x * 256 + threadIdx.x;
    if (i < Bn * Ln * Dn) out[i] = lat0[i % (Ln * Dn)];
}

// ---------------- per-head LayerNorm over head_dim=96 (in place) ----------------
// one block per row (H*HD=1536 elems), 16 warps = one head each
__global__ __launch_bounds__(512) void head_ln(
    float* __restrict__ x, const float* __restrict__ g, const float* __restrict__ b)
{
    const int row = blockIdx.x;
    const int w = threadIdx.x >> 5, lane = threadIdx.x & 31;
    float* p = x + (size_t)row * HHD + w * HDn;
    float a0 = p[lane], a1 = p[lane + 32], a2 = p[lane + 64];
    float s = a0 + a1 + a2;
    #pragma unroll
    for (int o = 16; o; o >>= 1) s += __shfl_xor_sync(0xffffffffu, s, o);
    const float mean = s * (1.f / HDn);
    float d0 = a0 - mean, d1 = a1 - mean, d2 = a2 - mean;
    float v = d0 * d0 + d1 * d1 + d2 * d2;
    #pragma unroll
    for (int o = 16; o; o >>= 1) v += __shfl_xor_sync(0xffffffffu, v, o);
    const float rstd = rsqrtf(v * (1.f / HDn) + EPSf);
    p[lane]      = d0 * rstd * g[lane]      + b[lane];
    p[lane + 32] = d1 * rstd * g[lane + 32] + b[lane + 32];
    p[lane + 64] = d2 * rstd * g[lane + 64] + b[lane + 64];
}

// ---------------- generic TF32 GEMM: C[M,N] = A[M,K] @ B[K,N] ----------------
// MODE_A: 0 plain, 1 per-column affine on A (a*g[k]+b[k]), K must be <= 1280
// EPI:    0 none, 1 relu, 2 add residual (res[M,N])
#define BM 128
#define BN 128
#define BK 32
#define PADA (BM + 8)   // 136: bank stride mod 32 == 8 -> conflict-free frag loads
#define PADB (BN + 8)   // 136

template<int MODE_A, int EPI>
__global__ __launch_bounds__(256) void gemm_tf32(
    const float* __restrict__ A, const float* __restrict__ B, float* __restrict__ C,
    int M, int N, int K,
    const float* __restrict__ ga, const float* __restrict__ ba,
    const float* __restrict__ res)
{
    __shared__ unsigned As[BK][PADA];
    __shared__ unsigned Bs[BK][PADB];
    __shared__ float gsh[MODE_A ? 1280 : 1];
    __shared__ float bsh[MODE_A ? 1280 : 1];

    const int tid  = threadIdx.x;
    const int lane = tid & 31;
    const int warp = tid >> 5;
    const int warpM = (warp >> 2) * 64;   // 2 warps along M
    const int warpN = (warp & 3) * 32;    // 4 warps along N

    const int nTilesN = N / BN;
    const int bidn = blockIdx.x % nTilesN;
    const int bidm = blockIdx.x / nTilesN;

    const float* Ablk = A + (size_t)bidm * BM * K;
    const float* Bblk = B + (size_t)bidn * BN;

    if (MODE_A) {
        for (int i = tid; i < K; i += 256) { gsh[i] = ga[i]; bsh[i] = ba[i]; }
    }

    float acc[4][4][4];
    #pragma unroll
    for (int i = 0; i < 4; i++)
        #pragma unroll
        for (int j = 0; j < 4; j++)
            #pragma unroll
            for (int q = 0; q < 4; q++) acc[i][j][q] = 0.f;

    if (MODE_A) __syncthreads();

    for (int k0 = 0; k0 < K; k0 += BK) {
        __syncthreads();
        // A tile: 128 rows x 32 k  (1024 float4, 4 per thread)
        #pragma unroll
        for (int it = 0; it < 4; it++) {
            int s = tid + it * 256;
            int rrow = s >> 3;
            int kq = (s & 7) * 4;
            float4 va = *(const float4*)(Ablk + (size_t)rrow * K + k0 + kq);
            if (MODE_A) {
                va.x = va.x * gsh[k0 + kq + 0] + bsh[k0 + kq + 0];
                va.y = va.y * gsh[k0 + kq + 1] + bsh[k0 + kq + 1];
                va.z = va.z * gsh[k0 + kq + 2] + bsh[k0 + kq + 2];
                va.w = va.w * gsh[k0 + kq + 3] + bsh[k0 + kq + 3];
            }
            As[kq + 0][rrow] = f2tf(va.x);
            As[kq + 1][rrow] = f2tf(va.y);
            As[kq + 2][rrow] = f2tf(va.z);
            As[kq + 3][rrow] = f2tf(va.w);
        }
        // B tile: 32 k-rows x 128 n
        #pragma unroll
        for (int it = 0; it < 4; it++) {
            int s = tid + it * 256;
            int kr = s >> 5;
            int nq = (s & 31) * 4;
            float4 vb = *(const float4*)(Bblk + (size_t)(k0 + kr) * N + nq);
            Bs[kr][nq + 0] = f2tf(vb.x);
            Bs[kr][nq + 1] = f2tf(vb.y);
            Bs[kr][nq + 2] = f2tf(vb.z);
            Bs[kr][nq + 3] = f2tf(vb.w);
        }
        __syncthreads();

        #pragma unroll
        for (int ks = 0; ks < 4; ks++) {
            unsigned af[4][4];
            unsigned bf[4][2];
            const int c = ks * 8 + (lane & 3);
            const int rbase = warpM + (lane >> 2);
            #pragma unroll
            for (int mt = 0; mt < 4; mt++) {
                int r = rbase + mt * 16;
                af[mt][0] = As[c][r];
                af[mt][1] = As[c][r + 8];
                af[mt][2] = As[c + 4][r];
                af[mt][3] = As[c + 4][r + 8];
            }
            const int cbase = warpN + (lane >> 2);
            #pragma unroll
            for (int nt = 0; nt < 4; nt++) {
                int cc = cbase + nt * 8;
                bf[nt][0] = Bs[c][cc];
                bf[nt][1] = Bs[c + 4][cc];
            }
            #pragma unroll
            for (int mt = 0; mt < 4; mt++)
                #pragma unroll
                for (int nt = 0; nt < 4; nt++)
                    mma_tf32(acc[mt][nt], af[mt], bf[nt]);
        }
    }

    // epilogue
    #pragma unroll
    for (int mt = 0; mt < 4; mt++) {
        int r = bidm * BM + warpM + mt * 16 + (lane >> 2);
        #pragma unroll
        for (int nt = 0; nt < 4; nt++) {
            int cc = bidn * BN + warpN + nt * 8 + 2 * (lane & 3);
            float v00 = acc[mt][nt][0], v01 = acc[mt][nt][1];
            float v10 = acc[mt][nt][2], v11 = acc[mt][nt][3];
            if (EPI == 1) {
                v00 = fmaxf(v00, 0.f); v01 = fmaxf(v01, 0.f);
                v10 = fmaxf(v10, 0.f); v11 = fmaxf(v11, 0.f);
            }
            if (EPI == 2) {
                v00 += res[(size_t)r * N + cc];
                v01 += res[(size_t)r * N + cc + 1];
                v10 += res[(size_t)(r + 8) * N + cc];
                v11 += res[(size_t)(r + 8) * N + cc + 1];
            }
            C[(size_t)r * N + cc]           = v00;
            C[(size_t)r * N + cc + 1]       = v01;
            C[(size_t)(r + 8) * N + cc]     = v10;
            C[(size_t)(r + 8) * N + cc + 1] = v11;
        }
    }
}

// ---------------- flash attention: one CTA per (b, h) ----------------
// Q[64,96] resident; 37 key tiles of 64 over concat(context, latents).
#define PQ 100   // stride mod 32 == 4 (row indexed by lane/4)
#define PK 100
#define PV 104   // stride mod 32 == 8 (row indexed by lane%4)
#define PP 68
#define ATTN_SMEM ((64*(PQ + PK + PV + PP)) * 4)

__global__ __launch_bounds__(128) void attn_kernel(
    const float* __restrict__ Qg, const float* __restrict__ Kc, const float* __restrict__ Kl,
    const float* __restrict__ Vc, const float* __restrict__ Vl, float* __restrict__ Og)
{
    extern __shared__ unsigned sm[];
    unsigned* Qs = sm;                 // [64][PQ]
    unsigned* Ks = Qs + 64 * PQ;       // [64][PK]
    unsigned* Vs = Ks + 64 * PK;       // [64][PV]
    unsigned* Ps = Vs + 64 * PV;       // [64][PP]

    const int b = blockIdx.x / Hn;
    const int h = blockIdx.x % Hn;
    const int tid = threadIdx.x;
    const int warp = tid >> 5, lane = tid & 31;
    const float scale = 0.10206207261596577f;  // 96^-0.5

    // load Q (scaled, tf32)
    for (int s = tid; s < 64 * 24; s += 128) {
        int q = s / 24, dq = (s % 24) * 4;
        float4 v = *(const float4*)(Qg + ((size_t)(b * Ln + q) * HHD) + h * HDn + dq);
        Qs[q * PQ + dq + 0] = f2tf(v.x * scale);
        Qs[q * PQ + dq + 1] = f2tf(v.y * scale);
        Qs[q * PQ + dq + 2] = f2tf(v.z * scale);
        Qs[q * PQ + dq + 3] = f2tf(v.w * scale);
    }

    float o[12][4];
    #pragma unroll
    for (int i = 0; i < 12; i++) { o[i][0] = o[i][1] = o[i][2] = o[i][3] = 0.f; }
    float m0 = -1e30f, m1 = -1e30f, l0 = 0.f, l1 = 0.f;

    const int r0loc = warp * 16 + (lane >> 2);   // this thread's two query rows
    const int nTiles = (Sn + Ln) / 64;           // 37

    for (int t = 0; t < nTiles; t++) {
        __syncthreads();  // protect K/V smem reuse
        const int kbase = t * 64;
        for (int s = tid; s < 64 * 24; s += 128) {
            int ky = s / 24, dq = (s % 24) * 4;
            int gk = kbase + ky;
            const float* srck = (gk < Sn)
                ? (Kc + (size_t)(b * Sn + gk) * HHD + h * HDn + dq)
                : (Kl + (size_t)(b * Ln + gk - Sn) * HHD + h * HDn + dq);
            const float* srcv = (gk < Sn)
                ? (Vc + (size_t)(b * Sn + gk) * HHD + h * HDn + dq)
                : (Vl + (size_t)(b * Ln + gk - Sn) * HHD + h * HDn + dq);
            float4 vk = *(const float4*)srck;
            float4 vv = *(const float4*)srcv;
            Ks[ky * PK + dq + 0] = f2tf(vk.x);
            Ks[ky * PK + dq + 1] = f2tf(vk.y);
            Ks[ky * PK + dq + 2] = f2tf(vk.z);
            Ks[ky * PK + dq + 3] = f2tf(vk.w);
            Vs[ky * PV + dq + 0] = f2tf(vv.x);
            Vs[ky * PV + dq + 1] = f2tf(vv.y);
            Vs[ky * PV + dq + 2] = f2tf(vv.z);
            Vs[ky * PV + dq + 3] = f2tf(vv.w);
        }
        __syncthreads();

        // S = Q @ K^T  (warp owns 16 query rows x 64 keys)
        float sf[8][4];
        #pragma unroll
        for (int nt = 0; nt < 8; nt++) { sf[nt][0] = sf[nt][1] = sf[nt][2] = sf[nt][3] = 0.f; }
        #pragma unroll
        for (int ks = 0; ks < 12; ks++) {
            const int c = ks * 8 + (lane & 3);
            unsigned a[4];
            a[0] = Qs[r0loc * PQ + c];
            a[1] = Qs[(r0loc + 8) * PQ + c];
            a[2] = Qs[r0loc * PQ + c + 4];
            a[3] = Qs[(r0loc + 8) * PQ + c + 4];
            #pragma unroll
            for (int nt = 0; nt < 8; nt++) {
                unsigned bb[2];
                int key = nt * 8 + (lane >> 2);
                bb[0] = Ks[key * PK + c];
                bb[1] = Ks[key * PK + c + 4];
                mma_tf32(sf[nt], a, bb);
            }
        }

        // online softmax
        float mt0 = -1e30f, mt1 = -1e30f;
        #pragma unroll
        for (int nt = 0; nt < 8; nt++) {
            mt0 = fmaxf(mt0, fmaxf(sf[nt][0], sf[nt][1]));
            mt1 = fmaxf(mt1, fmaxf(sf[nt][2], sf[nt][3]));
        }
        mt0 = fmaxf(mt0, __shfl_xor_sync(0xffffffffu, mt0, 1));
        mt0 = fmaxf(mt0, __shfl_xor_sync(0xffffffffu, mt0, 2));
        mt1 = fmaxf(mt1, __shfl_xor_sync(0xffffffffu, mt1, 1));
        mt1 = fmaxf(mt1, __shfl_xor_sync(0xffffffffu, mt1, 2));
        const float mn0 = fmaxf(m0, mt0), mn1 = fmaxf(m1, mt1);
        const float al0 = __expf(m0 - mn0), al1 = __expf(m1 - mn1);
        m0 = mn0; m1 = mn1;

        float ps0 = 0.f, ps1 = 0.f;
        #pragma unroll
        for (int nt = 0; nt < 8; nt++) {
            int cc = nt * 8 + 2 * (lane & 3);
            float p00 = __expf(sf[nt][0] - mn0);
            float p01 = __expf(sf[nt][1] - mn0);
            float p10 = __expf(sf[nt][2] - mn1);
            float p11 = __expf(sf[nt][3] - mn1);
            ps0 += p00 + p01;
            ps1 += p10 + p11;
            Ps[r0loc * PP + cc]           = f2tf(p00);
            Ps[r0loc * PP + cc + 1]       = f2tf(p01);
            Ps[(r0loc + 8) * PP + cc]     = f2tf(p10);
            Ps[(r0loc + 8) * PP + cc + 1] = f2tf(p11);
        }
        ps0 += __shfl_xor_sync(0xffffffffu, ps0, 1);
        ps0 += __shfl_xor_sync(0xffffffffu, ps0, 2);
        ps1 += __shfl_xor_sync(0xffffffffu, ps1, 1);
        ps1 += __shfl_xor_sync(0xffffffffu, ps1, 2);
        l0 = l0 * al0 + ps0;
        l1 = l1 * al1 + ps1;

        #pragma unroll
        for (int i = 0; i < 12; i++) {
            o[i][0] *= al0; o[i][1] *= al0;
            o[i][2] *= al1; o[i][3] *= al1;
        }
        __syncwarp();

        // O += P @ V   (K = 64 keys -> 8 ksteps; N = 96 -> 12 ntiles)
        #pragma unroll
        for (int ks = 0; ks < 8; ks++) {
            const int kk = ks * 8 + (lane & 3);
            unsigned a[4];
            a[0] = Ps[r0loc * PP + kk];
            a[1] = Ps[(r0loc + 8) * PP + kk];
            a[2] = Ps[r0loc * PP + kk + 4];
            a[3] = Ps[(r0loc + 8) * PP + kk + 4];
            #pragma unroll
            for (int nt = 0; nt < 12; nt++) {
                unsigned bb[2];
                int n = nt * 8 + (lane >> 2);
                bb[0] = Vs[kk * PV + n];
                bb[1] = Vs[(kk + 4) * PV + n];
                mma_tf32(o[nt], a, bb);
            }
        }
    }

    // normalize and write [b, q, h*96 + c]
    const float inv0 = 1.f / l0, inv1 = 1.f / l1;
    #pragma unroll
    for (int nt = 0; nt < 12; nt++) {
        int cc = nt * 8 + 2 * (lane & 3);
        size_t base0 = (size_t)(b * Ln + r0loc) * HHD + h * HDn + cc;
        size_t base1 = (size_t)(b * Ln + r0loc + 8) * HHD + h * HDn + cc;
        Og[base0]     = o[nt][0] * inv0;
        Og[base0 + 1] = o[nt][1] * inv0;
        Og[base1]     = o[nt][2] * inv1;
        Og[base1 + 1] = o[nt][3] * inv1;
    }
}

// ---------------- host orchestration ----------------
extern "C" void kernel_launch(void* const* d_in, const int* in_sizes, int n_in,
                              void* d_out, int out_size)
{
    const float* context = (const float*)d_in[0];
    const float* latents = (const float*)d_in[1];
    const float* ctx_g   = (const float*)d_in[2];
    const float* ctx_b   = (const float*)d_in[3];
    const float* lat_g   = (const float*)d_in[4];
    const float* lat_b   = (const float*)d_in[5];
    const float* q_g     = (const float*)d_in[6];
    const float* q_b     = (const float*)d_in[7];
    const float* k_g     = (const float*)d_in[8];
    const float* k_b     = (const float*)d_in[9];
    const float* Wq      = (const float*)d_in[10];
    const float* Wk      = (const float*)d_in[11];
    const float* Wv      = (const float*)d_in[12];
    const float* Wo      = (const float*)d_in[13];
    const float* mlp_g   = (const float*)d_in[14];
    const float* mlp_b   = (const float*)d_in[15];
    const float* Wfc     = (const float*)d_in[16];
    const float* Wcp     = (const float*)d_in[17];
    const float* f_g     = (const float*)d_in[18];
    const float* f_b     = (const float*)d_in[19];
    float* out = (float*)d_out;

    float *xhat, *lat, *lhat, *mlph, *Kc, *Vc, *Qb, *Kl, *Vl, *att, *hid;
    cudaGetSymbolAddress((void**)&xhat, g_xhat);
    cudaGetSymbolAddress((void**)&lat,  g_lat);
    cudaGetSymbolAddress((void**)&lhat, g_lhat);
    cudaGetSymbolAddress((void**)&mlph, g_mlph);
    cudaGetSymbolAddress((void**)&Kc,   g_Kc);
    cudaGetSymbolAddress((void**)&Vc,   g_Vc);
    cudaGetSymbolAddress((void**)&Qb,   g_Q);
    cudaGetSymbolAddress((void**)&Kl,   g_Kl);
    cudaGetSymbolAddress((void**)&Vl,   g_Vl);
    cudaGetSymbolAddress((void**)&att,  g_att);
    cudaGetSymbolAddress((void**)&hid,  g_hid);

    cudaFuncSetAttribute(attn_kernel, cudaFuncAttributeMaxDynamicSharedMemorySize, ATTN_SMEM);

    const int MBIG = Bn * Sn;   // 73728
    const int MLAT = Bn * Ln;   // 2048

    // context LN (once; per-layer gamma/beta folded into GEMM A-load)
    ln_kernel<false><<<MBIG, 256>>>(context, xhat, nullptr, nullptr);
    bcast_lat<<<(Bn * Ln * Dn + 255) / 256, 256>>>(latents, lat);

    for (int i = 0; i < DEPTHn; i++) {
        const float* Wqi  = Wq  + (size_t)i * Dn * HHD;
        const float* Wki  = Wk  + (size_t)i * Dn * HHD;
        const float* Wvi  = Wv  + (size_t)i * Dn * HHD;
        const float* Woi  = Wo  + (size_t)i * HHD * Dn;
        const float* Wfci = Wfc + (size_t)i * Dn * INTERn;
        const float* Wcpi = Wcp + (size_t)i * INTERn * Dn;

        ln_kernel<true><<<MLAT, 256>>>(lat, lhat, lat_g + i * Dn, lat_b + i * Dn);

        // context K/V projections (dominant cost)
        gemm_tf32<1,0><<<(MBIG/BM)*(HHD/BN), 256>>>(xhat, Wki, Kc, MBIG, HHD, Dn,
                                                    ctx_g + i * Dn, ctx_b + i * Dn, nullptr);
        gemm_tf32<1,0><<<(MBIG/BM)*(HHD/BN), 256>>>(xhat, Wvi, Vc, MBIG, HHD, Dn,
                                                    ctx_g + i * Dn, ctx_b + i * Dn, nullptr);
        // latent Q/K/V
        gemm_tf32<0,0><<<(MLAT/BM)*(HHD/BN), 256>>>(lhat, Wqi, Qb, MLAT, HHD, Dn,
                                                    nullptr, nullptr, nullptr);
        gemm_tf32<0,0><<<(MLAT/BM)*(HHD/BN), 256>>>(lhat, Wki, Kl, MLAT, HHD, Dn,
                                                    nullptr, nullptr, nullptr);
        gemm_tf32<0,0><<<(MLAT/BM)*(HHD/BN), 256>>>(lhat, Wvi, Vl, MLAT, HHD, Dn,
                                                    nullptr, nullptr, nullptr);
        // per-head QK layer norms
        head_ln<<<MLAT, 512>>>(Qb, q_g + i * HDn, q_b + i * HDn);
        head_ln<<<MBIG, 512>>>(Kc, k_g + i * HDn, k_b + i * HDn);
        head_ln<<<MLAT, 512>>>(Kl, k_g + i * HDn, k_b + i * HDn);

        attn_kernel<<<Bn * Hn, 128, ATTN_SMEM>>>(Qb, Kc, Kl, Vc, Vl, att);

        // output projection + residual
        gemm_tf32<0,2><<<(MLAT/BM)*(Dn/BN), 256>>>(att, Woi, lat, MLAT, Dn, HHD,
                                                   nullptr, nullptr, lat);
        // MLP
        ln_kernel<true><<<MLAT, 256>>>(lat, mlph, mlp_g + i * Dn, mlp_b + i * Dn);
        gemm_tf32<0,1><<<(MLAT/BM)*(INTERn/BN), 256>>>(mlph, Wfci, hid, MLAT, INTERn, Dn,
                                                       nullptr, nullptr, nullptr);
        gemm_tf32<0,2><<<(MLAT/BM)*(Dn/BN), 256>>>(hid, Wcpi, lat, MLAT, Dn, INTERn,
                                                   nullptr, nullptr, lat);
    }

    ln_kernel<true><<<MLAT, 256>>>(lat, out, f_g, f_b);
}

// round 12
// speedup vs baseline: 1.2887x; 1.2887x over previous
#include <cuda_runtime.h>
#include <cuda_bf16.h>
#include <math.h>

// ---------------- problem constants ----------------
#define Bn     32
#define Sn     2304
#define Dn     1280
#define Hn     16
#define HDn    96
#define HHD    1536      // Hn*HDn
#define Ln     64
#define INTERn 5120
#define DEPTHn 6
#define EPSf   1e-5f

// ---------------- scratch: __device__ globals (no cudaMalloc allowed) ----------------
__device__ float g_xhat[(size_t)Bn*Sn*Dn];      // normalized context (layer-independent)
__device__ float g_lat [(size_t)Bn*Ln*Dn];      // latent residual stream
__device__ float g_lhat[(size_t)Bn*Ln*Dn];      // LN(lat) for attention block
__device__ float g_mlph[(size_t)Bn*Ln*Dn];      // LN(lat) for MLP block
__device__ float g_Kc  [(size_t)Bn*Sn*HHD];     // context K (head-LN applied in place)
__device__ float g_Vc  [(size_t)Bn*Sn*HHD];     // context V
__device__ float g_Q   [(size_t)Bn*Ln*HHD];
__device__ float g_Kl  [(size_t)Bn*Ln*HHD];     // latent K
__device__ float g_Vl  [(size_t)Bn*Ln*HHD];     // latent V
__device__ float g_att [(size_t)Bn*Ln*HHD];     // attention output (heads merged)
__device__ float g_hid [(size_t)Bn*Ln*INTERn];  // MLP hidden

// ---------------- helpers ----------------
__device__ __forceinline__ unsigned f2tf(float x) {
    unsigned r;
    asm("cvt.rna.tf32.f32 %0, %1;" : "=r"(r) : "f"(x));
    return r;
}

__device__ __forceinline__ void mma_tf32(float* c, const unsigned* a, const unsigned* b) {
    asm volatile(
        "mma.sync.aligned.m16n8k8.row.col.f32.tf32.tf32.f32 "
        "{%0,%1,%2,%3}, {%4,%5,%6,%7}, {%8,%9}, {%0,%1,%2,%3};\n"
        : "+f"(c[0]), "+f"(c[1]), "+f"(c[2]), "+f"(c[3])
        : "r"(a[0]), "r"(a[1]), "r"(a[2]), "r"(a[3]), "r"(b[0]), "r"(b[1]));
}

// ---------------- row LayerNorm, width = 1280 ----------------
template<bool AFF>
__global__ __launch_bounds__(256) void ln_kernel(
    const float* __restrict__ in, float* __restrict__ out,
    const float* __restrict__ g, const float* __restrict__ b)
{
    __shared__ float row[Dn];
    __shared__ float red[8];
    __shared__ float stat[2];
    const int r = blockIdx.x, tid = threadIdx.x;
    const int lane = tid & 31, w = tid >> 5;
    const float* x = in + (size_t)r * Dn;

    float s = 0.f;
    for (int i = tid; i < Dn; i += 256) { float v = x[i]; row[i] = v; s += v; }
    #pragma unroll
    for (int o = 16; o; o >>= 1) s += __shfl_xor_sync(0xffffffffu, s, o);
    if (lane == 0) red[w] = s;
    __syncthreads();
    if (tid == 0) { float t = 0.f; for (int j = 0; j < 8; j++) t += red[j]; stat[0] = t * (1.f/Dn); }
    __syncthreads();
    const float mean = stat[0];

    float s2 = 0.f;
    for (int i = tid; i < Dn; i += 256) { float d = row[i] - mean; s2 += d * d; }
    #pragma unroll
    for (int o = 16; o; o >>= 1) s2 += __shfl_xor_sync(0xffffffffu, s2, o);
    if (lane == 0) red[w] = s2;
    __syncthreads();
    if (tid == 0) { float t = 0.f; for (int j = 0; j < 8; j++) t += red[j]; stat[1] = rsqrtf(t * (1.f/Dn) + EPSf); }
    __syncthreads();
    const float rstd = stat[1];

    float* o = out + (size_t)r * Dn;
    for (int i = tid; i < Dn; i += 256) {
        float v = (row[i] - mean) * rstd;
        o[i] = AFF ? (v * g[i] + b[i]) : v;
    }
}

// ---------------- broadcast latents to batch ----------------
__global__ void bcast_lat(const float* __restrict__ lat0, float* __restrict__ out) {
    int i = blockIdx.x * 256 + threadIdx.x;
    if (i < Bn * Ln * Dn) out[i] = lat0[i % (Ln * Dn)];
}

// ---------------- per-head LayerNorm over head_dim=96 (in place) ----------------
__global__ __launch_bounds__(512) void head_ln(
    float* __restrict__ x, const float* __restrict__ g, const float* __restrict__ b)
{
    const int row = blockIdx.x;
    const int w = threadIdx.x >> 5, lane = threadIdx.x & 31;
    float* p = x + (size_t)row * HHD + w * HDn;
    float a0 = p[lane], a1 = p[lane + 32], a2 = p[lane + 64];
    float s = a0 + a1 + a2;
    #pragma unroll
    for (int o = 16; o; o >>= 1) s += __shfl_xor_sync(0xffffffffu, s, o);
    const float mean = s * (1.f / HDn);
    float d0 = a0 - mean, d1 = a1 - mean, d2 = a2 - mean;
    float v = d0 * d0 + d1 * d1 + d2 * d2;
    #pragma unroll
    for (int o = 16; o; o >>= 1) v += __shfl_xor_sync(0xffffffffu, v, o);
    const float rstd = rsqrtf(v * (1.f / HDn) + EPSf);
    p[lane]      = d0 * rstd * g[lane]      + b[lane];
    p[lane + 32] = d1 * rstd * g[lane + 32] + b[lane + 32];
    p[lane + 64] = d2 * rstd * g[lane + 64] + b[lane + 64];
}

// ---------------- generic TF32 GEMM: C[M,N] = A[M,K] @ B[K,N] ----------------
// MODE_A: 0 plain, 1 per-column affine on A (a*g[k]+b[k]), K must be <= 1280
// EPI:    0 none, 1 relu, 2 add residual (res[M,N])
#define BM 128
#define BN 128
#define BK 32
// A stored ROW-major [BM][BK+4]: stride 36 words -> 36 mod 32 = 4.
//   frag load bank = 4*(lane>>2) + (lane&3): all 32 banks, conflict-free.
//   staging: STS.128, each 8-lane phase covers 32 consecutive words, conflict-free.
#define PADA_K (BK + 4)   // 36
// B stored K-major [BK][BN+8]: stride 136 -> 8 mod 32.
//   frag load bank = 8*(lane&3) + (lane>>2): conflict-free.
//   staging: STS.128 covering 128 consecutive words per warp, conflict-free.
#define PADB (BN + 8)     // 136

template<int MODE_A, int EPI>
__global__ __launch_bounds__(256) void gemm_tf32(
    const float* __restrict__ A, const float* __restrict__ B, float* __restrict__ C,
    int M, int N, int K,
    const float* __restrict__ ga, const float* __restrict__ ba,
    const float* __restrict__ res)
{
    __shared__ unsigned As[BM][PADA_K];
    __shared__ unsigned Bs[BK][PADB];
    __shared__ float gsh[MODE_A ? 1280 : 1];
    __shared__ float bsh[MODE_A ? 1280 : 1];

    const int tid  = threadIdx.x;
    const int lane = tid & 31;
    const int warp = tid >> 5;
    const int warpM = (warp >> 2) * 64;   // 2 warps along M
    const int warpN = (warp & 3) * 32;    // 4 warps along N

    const int nTilesN = N / BN;
    const int bidn = blockIdx.x % nTilesN;
    const int bidm = blockIdx.x / nTilesN;

    const float* Ablk = A + (size_t)bidm * BM * K;
    const float* Bblk = B + (size_t)bidn * BN;

    if (MODE_A) {
        for (int i = tid; i < K; i += 256) { gsh[i] = ga[i]; bsh[i] = ba[i]; }
    }

    float acc[4][4][4];
    #pragma unroll
    for (int i = 0; i < 4; i++)
        #pragma unroll
        for (int j = 0; j < 4; j++)
            #pragma unroll
            for (int q = 0; q < 4; q++) acc[i][j][q] = 0.f;

    if (MODE_A) __syncthreads();

    for (int k0 = 0; k0 < K; k0 += BK) {
        __syncthreads();
        // A tile: 128 rows x 32 k. Row-major smem; one STS.128 per thread per it.
        #pragma unroll
        for (int it = 0; it < 4; it++) {
            int s = tid + it * 256;
            int rrow = s >> 3;
            int kq = (s & 7) * 4;
            float4 va = *(const float4*)(Ablk + (size_t)rrow * K + k0 + kq);
            if (MODE_A) {
                va.x = va.x * gsh[k0 + kq + 0] + bsh[k0 + kq + 0];
                va.y = va.y * gsh[k0 + kq + 1] + bsh[k0 + kq + 1];
                va.z = va.z * gsh[k0 + kq + 2] + bsh[k0 + kq + 2];
                va.w = va.w * gsh[k0 + kq + 3] + bsh[k0 + kq + 3];
            }
            uint4 ua;
            ua.x = f2tf(va.x); ua.y = f2tf(va.y); ua.z = f2tf(va.z); ua.w = f2tf(va.w);
            *(uint4*)&As[rrow][kq] = ua;
        }
        // B tile: 32 k-rows x 128 n. One STS.128 per thread per it.
        #pragma unroll
        for (int it = 0; it < 4; it++) {
            int s = tid + it * 256;
            int kr = s >> 5;
            int nq = (s & 31) * 4;
            float4 vb = *(const float4*)(Bblk + (size_t)(k0 + kr) * N + nq);
            uint4 ub;
            ub.x = f2tf(vb.x); ub.y = f2tf(vb.y); ub.z = f2tf(vb.z); ub.w = f2tf(vb.w);
            *(uint4*)&Bs[kr][nq] = ub;
        }
        __syncthreads();

        #pragma unroll
        for (int ks = 0; ks < 4; ks++) {
            unsigned af[4][4];
            unsigned bf[4][2];
            const int c = ks * 8 + (lane & 3);
            const int rbase = warpM + (lane >> 2);
            #pragma unroll
            for (int mt = 0; mt < 4; mt++) {
                int r = rbase + mt * 16;
                af[mt][0] = As[r][c];
                af[mt][1] = As[r + 8][c];
                af[mt][2] = As[r][c + 4];
                af[mt][3] = As[r + 8][c + 4];
            }
            const int cbase = warpN + (lane >> 2);
            #pragma unroll
            for (int nt = 0; nt < 4; nt++) {
                int cc = cbase + nt * 8;
                bf[nt][0] = Bs[c][cc];
                bf[nt][1] = Bs[c + 4][cc];
            }
            #pragma unroll
            for (int mt = 0; mt < 4; mt++)
                #pragma unroll
                for (int nt = 0; nt < 4; nt++)
                    mma_tf32(acc[mt][nt], af[mt], bf[nt]);
        }
    }

    // epilogue
    #pragma unroll
    for (int mt = 0; mt < 4; mt++) {
        int r = bidm * BM + warpM + mt * 16 + (lane >> 2);
        #pragma unroll
        for (int nt = 0; nt < 4; nt++) {
            int cc = bidn * BN + warpN + nt * 8 + 2 * (lane & 3);
            float v00 = acc[mt][nt][0], v01 = acc[mt][nt][1];
            float v10 = acc[mt][nt][2], v11 = acc[mt][nt][3];
            if (EPI == 1) {
                v00 = fmaxf(v00, 0.f); v01 = fmaxf(v01, 0.f);
                v10 = fmaxf(v10, 0.f); v11 = fmaxf(v11, 0.f);
            }
            if (EPI == 2) {
                v00 += res[(size_t)r * N + cc];
                v01 += res[(size_t)r * N + cc + 1];
                v10 += res[(size_t)(r + 8) * N + cc];
                v11 += res[(size_t)(r + 8) * N + cc + 1];
            }
            C[(size_t)r * N + cc]           = v00;
            C[(size_t)r * N + cc + 1]       = v01;
            C[(size_t)(r + 8) * N + cc]     = v10;
            C[(size_t)(r + 8) * N + cc + 1] = v11;
        }
    }
}

// ---------------- flash attention: one CTA per (b, h) ----------------
#define PQ 100   // stride mod 32 == 4 (row indexed by lane/4)
#define PK 100
#define PV 104   // stride mod 32 == 8 (row indexed by lane%4)
#define PP 68
#define ATTN_SMEM ((64*(PQ + PK + PV + PP)) * 4)

__global__ __launch_bounds__(128) void attn_kernel(
    const float* __restrict__ Qg, const float* __restrict__ Kc, const float* __restrict__ Kl,
    const float* __restrict__ Vc, const float* __restrict__ Vl, float* __restrict__ Og)
{
    extern __shared__ unsigned sm[];
    unsigned* Qs = sm;                 // [64][PQ]
    unsigned* Ks = Qs + 64 * PQ;       // [64][PK]
    unsigned* Vs = Ks + 64 * PK;       // [64][PV]
    unsigned* Ps = Vs + 64 * PV;       // [64][PP]

    const int b = blockIdx.x / Hn;
    const int h = blockIdx.x % Hn;
    const int tid = threadIdx.x;
    const int warp = tid >> 5, lane = tid & 31;
    const float scale = 0.10206207261596577f;  // 96^-0.5

    for (int s = tid; s < 64 * 24; s += 128) {
        int q = s / 24, dq = (s % 24) * 4;
        float4 v = *(const float4*)(Qg + ((size_t)(b * Ln + q) * HHD) + h * HDn + dq);
        Qs[q * PQ + dq + 0] = f2tf(v.x * scale);
        Qs[q * PQ + dq + 1] = f2tf(v.y * scale);
        Qs[q * PQ + dq + 2] = f2tf(v.z * scale);
        Qs[q * PQ + dq + 3] = f2tf(v.w * scale);
    }

    float o[12][4];
    #pragma unroll
    for (int i = 0; i < 12; i++) { o[i][0] = o[i][1] = o[i][2] = o[i][3] = 0.f; }
    float m0 = -1e30f, m1 = -1e30f, l0 = 0.f, l1 = 0.f;

    const int r0loc = warp * 16 + (lane >> 2);
    const int nTiles = (Sn + Ln) / 64;           // 37

    for (int t = 0; t < nTiles; t++) {
        __syncthreads();
        const int kbase = t * 64;
        for (int s = tid; s < 64 * 24; s += 128) {
            int ky = s / 24, dq = (s % 24) * 4;
            int gk = kbase + ky;
            const float* srck = (gk < Sn)
                ? (Kc + (size_t)(b * Sn + gk) * HHD + h * HDn + dq)
                : (Kl + (size_t)(b * Ln + gk - Sn) * HHD + h * HDn + dq);
            const float* srcv = (gk < Sn)
                ? (Vc + (size_t)(b * Sn + gk) * HHD + h * HDn + dq)
                : (Vl + (size_t)(b * Ln + gk - Sn) * HHD + h * HDn + dq);
            float4 vk = *(const float4*)srck;
            float4 vv = *(const float4*)srcv;
            Ks[ky * PK + dq + 0] = f2tf(vk.x);
            Ks[ky * PK + dq + 1] = f2tf(vk.y);
            Ks[ky * PK + dq + 2] = f2tf(vk.z);
            Ks[ky * PK + dq + 3] = f2tf(vk.w);
            Vs[ky * PV + dq + 0] = f2tf(vv.x);
            Vs[ky * PV + dq + 1] = f2tf(vv.y);
            Vs[ky * PV + dq + 2] = f2tf(vv.z);
            Vs[ky * PV + dq + 3] = f2tf(vv.w);
        }
        __syncthreads();

        float sf[8][4];
        #pragma unroll
        for (int nt = 0; nt < 8; nt++) { sf[nt][0] = sf[nt][1] = sf[nt][2] = sf[nt][3] = 0.f; }
        #pragma unroll
        for (int ks = 0; ks < 12; ks++) {
            const int c = ks * 8 + (lane & 3);
            unsigned a[4];
            a[0] = Qs[r0loc * PQ + c];
            a[1] = Qs[(r0loc + 8) * PQ + c];
            a[2] = Qs[r0loc * PQ + c + 4];
            a[3] = Qs[(r0loc + 8) * PQ + c + 4];
            #pragma unroll
            for (int nt = 0; nt < 8; nt++) {
                unsigned bb[2];
                int key = nt * 8 + (lane >> 2);
                bb[0] = Ks[key * PK + c];
                bb[1] = Ks[key * PK + c + 4];
                mma_tf32(sf[nt], a, bb);
            }
        }

        float mt0 = -1e30f, mt1 = -1e30f;
        #pragma unroll
        for (int nt = 0; nt < 8; nt++) {
            mt0 = fmaxf(mt0, fmaxf(sf[nt][0], sf[nt][1]));
            mt1 = fmaxf(mt1, fmaxf(sf[nt][2], sf[nt][3]));
        }
        mt0 = fmaxf(mt0, __shfl_xor_sync(0xffffffffu, mt0, 1));
        mt0 = fmaxf(mt0, __shfl_xor_sync(0xffffffffu, mt0, 2));
        mt1 = fmaxf(mt1, __shfl_xor_sync(0xffffffffu, mt1, 1));
        mt1 = fmaxf(mt1, __shfl_xor_sync(0xffffffffu, mt1, 2));
        const float mn0 = fmaxf(m0, mt0), mn1 = fmaxf(m1, mt1);
        const float al0 = __expf(m0 - mn0), al1 = __expf(m1 - mn1);
        m0 = mn0; m1 = mn1;

        float ps0 = 0.f, ps1 = 0.f;
        #pragma unroll
        for (int nt = 0; nt < 8; nt++) {
            int cc = nt * 8 + 2 * (lane & 3);
            float p00 = __expf(sf[nt][0] - mn0);
            float p01 = __expf(sf[nt][1] - mn0);
            float p10 = __expf(sf[nt][2] - mn1);
            float p11 = __expf(sf[nt][3] - mn1);
            ps0 += p00 + p01;
            ps1 += p10 + p11;
            Ps[r0loc * PP + cc]           = f2tf(p00);
            Ps[r0loc * PP + cc + 1]       = f2tf(p01);
            Ps[(r0loc + 8) * PP + cc]     = f2tf(p10);
            Ps[(r0loc + 8) * PP + cc + 1] = f2tf(p11);
        }
        ps0 += __shfl_xor_sync(0xffffffffu, ps0, 1);
        ps0 += __shfl_xor_sync(0xffffffffu, ps0, 2);
        ps1 += __shfl_xor_sync(0xffffffffu, ps1, 1);
        ps1 += __shfl_xor_sync(0xffffffffu, ps1, 2);
        l0 = l0 * al0 + ps0;
        l1 = l1 * al1 + ps1;

        #pragma unroll
        for (int i = 0; i < 12; i++) {
            o[i][0] *= al0; o[i][1] *= al0;
            o[i][2] *= al1; o[i][3] *= al1;
        }
        __syncwarp();

        #pragma unroll
        for (int ks = 0; ks < 8; ks++) {
            const int kk = ks * 8 + (lane & 3);
            unsigned a[4];
            a[0] = Ps[r0loc * PP + kk];
            a[1] = Ps[(r0loc + 8) * PP + kk];
            a[2] = Ps[r0loc * PP + kk + 4];
            a[3] = Ps[(r0loc + 8) * PP + kk + 4];
            #pragma unroll
            for (int nt = 0; nt < 12; nt++) {
                unsigned bb[2];
                int n = nt * 8 + (lane >> 2);
                bb[0] = Vs[kk * PV + n];
                bb[1] = Vs[(kk + 4) * PV + n];
                mma_tf32(o[nt], a, bb);
            }
        }
    }

    const float inv0 = 1.f / l0, inv1 = 1.f / l1;
    #pragma unroll
    for (int nt = 0; nt < 12; nt++) {
        int cc = nt * 8 + 2 * (lane & 3);
        size_t base0 = (size_t)(b * Ln + r0loc) * HHD + h * HDn + cc;
        size_t base1 = (size_t)(b * Ln + r0loc + 8) * HHD + h * HDn + cc;
        Og[base0]     = o[nt][0] * inv0;
        Og[base0 + 1] = o[nt][1] * inv0;
        Og[base1]     = o[nt][2] * inv1;
        Og[base1 + 1] = o[nt][3] * inv1;
    }
}

// ---------------- host orchestration ----------------
extern "C" void kernel_launch(void* const* d_in, const int* in_sizes, int n_in,
                              void* d_out, int out_size)
{
    const float* context = (const float*)d_in[0];
    const float* latents = (const float*)d_in[1];
    const float* ctx_g   = (const float*)d_in[2];
    const float* ctx_b   = (const float*)d_in[3];
    const float* lat_g   = (const float*)d_in[4];
    const float* lat_b   = (const float*)d_in[5];
    const float* q_g     = (const float*)d_in[6];
    const float* q_b     = (const float*)d_in[7];
    const float* k_g     = (const float*)d_in[8];
    const float* k_b     = (const float*)d_in[9];
    const float* Wq      = (const float*)d_in[10];
    const float* Wk      = (const float*)d_in[11];
    const float* Wv      = (const float*)d_in[12];
    const float* Wo      = (const float*)d_in[13];
    const float* mlp_g   = (const float*)d_in[14];
    const float* mlp_b   = (const float*)d_in[15];
    const float* Wfc     = (const float*)d_in[16];
    const float* Wcp     = (const float*)d_in[17];
    const float* f_g     = (const float*)d_in[18];
    const float* f_b     = (const float*)d_in[19];
    float* out = (float*)d_out;

    float *xhat, *lat, *lhat, *mlph, *Kc, *Vc, *Qb, *Kl, *Vl, *att, *hid;
    cudaGetSymbolAddress((void**)&xhat, g_xhat);
    cudaGetSymbolAddress((void**)&lat,  g_lat);
    cudaGetSymbolAddress((void**)&lhat, g_lhat);
    cudaGetSymbolAddress((void**)&mlph, g_mlph);
    cudaGetSymbolAddress((void**)&Kc,   g_Kc);
    cudaGetSymbolAddress((void**)&Vc,   g_Vc);
    cudaGetSymbolAddress((void**)&Qb,   g_Q);
    cudaGetSymbolAddress((void**)&Kl,   g_Kl);
    cudaGetSymbolAddress((void**)&Vl,   g_Vl);
    cudaGetSymbolAddress((void**)&att,  g_att);
    cudaGetSymbolAddress((void**)&hid,  g_hid);

    cudaFuncSetAttribute(attn_kernel, cudaFuncAttributeMaxDynamicSharedMemorySize, ATTN_SMEM);

    const int MBIG = Bn * Sn;   // 73728
    const int MLAT = Bn * Ln;   // 2048

    // context LN (once; per-layer gamma/beta folded into GEMM A-load)
    ln_kernel<false><<<MBIG, 256>>>(context, xhat, nullptr, nullptr);
    bcast_lat<<<(Bn * Ln * Dn + 255) / 256, 256>>>(latents, lat);

    for (int i = 0; i < DEPTHn; i++) {
        const float* Wqi  = Wq  + (size_t)i * Dn * HHD;
        const float* Wki  = Wk  + (size_t)i * Dn * HHD;
        const float* Wvi  = Wv  + (size_t)i * Dn * HHD;
        const float* Woi  = Wo  + (size_t)i * HHD * Dn;
        const float* Wfci = Wfc + (size_t)i * Dn * INTERn;
        const float* Wcpi = Wcp + (size_t)i * INTERn * Dn;

        ln_kernel<true><<<MLAT, 256>>>(lat, lhat, lat_g + i * Dn, lat_b + i * Dn);

        // context K/V projections (dominant cost)
        gemm_tf32<1,0><<<(MBIG/BM)*(HHD/BN), 256>>>(xhat, Wki, Kc, MBIG, HHD, Dn,
                                                    ctx_g + i * Dn, ctx_b + i * Dn, nullptr);
        gemm_tf32<1,0><<<(MBIG/BM)*(HHD/BN), 256>>>(xhat, Wvi, Vc, MBIG, HHD, Dn,
                                                    ctx_g + i * Dn, ctx_b + i * Dn, nullptr);
        // latent Q/K/V
        gemm_tf32<0,0><<<(MLAT/BM)*(HHD/BN), 256>>>(lhat, Wqi, Qb, MLAT, HHD, Dn,
                                                    nullptr, nullptr, nullptr);
        gemm_tf32<0,0><<<(MLAT/BM)*(HHD/BN), 256>>>(lhat, Wki, Kl, MLAT, HHD, Dn,
                                                    nullptr, nullptr, nullptr);
        gemm_tf32<0,0><<<(MLAT/BM)*(HHD/BN), 256>>>(lhat, Wvi, Vl, MLAT, HHD, Dn,
                                                    nullptr, nullptr, nullptr);
        // per-head QK layer norms
        head_ln<<<MLAT, 512>>>(Qb, q_g + i * HDn, q_b + i * HDn);
        head_ln<<<MBIG, 512>>>(Kc, k_g + i * HDn, k_b + i * HDn);
        head_ln<<<MLAT, 512>>>(Kl, k_g + i * HDn, k_b + i * HDn);

        attn_kernel<<<Bn * Hn, 128, ATTN_SMEM>>>(Qb, Kc, Kl, Vc, Vl, att);

        // output projection + residual
        gemm_tf32<0,2><<<(MLAT/BM)*(Dn/BN), 256>>>(att, Woi, lat, MLAT, Dn, HHD,
                                                   nullptr, nullptr, lat);
        // MLP
        ln_kernel<true><<<MLAT, 256>>>(lat, mlph, mlp_g + i * Dn, mlp_b + i * Dn);
        gemm_tf32<0,1><<<(MLAT/BM)*(INTERn/BN), 256>>>(mlph, Wfci, hid, MLAT, INTERn, Dn,
                                                       nullptr, nullptr, nullptr);
        gemm_tf32<0,2><<<(MLAT/BM)*(Dn/BN), 256>>>(hid, Wcpi, lat, MLAT, Dn, INTERn,
                                                   nullptr, nullptr, lat);
    }

    ln_kernel<true><<<MLAT, 256>>>(lat, out, f_g, f_b);
}